// round 2
// baseline (speedup 1.0000x reference)
#include <cuda_runtime.h>

// Residual VQ: x [N,128] fp32, codebooks [S,256,128] fp32.
// Output layout (float32): x_q [N*128], mean_loss [1], indices [N*S] (as floats).
//
// One CTA processes 128 rows through all S stages:
//   stage: load codebook (swizzled, transposed) into SMEM -> GEMM dots ->
//          argmin(||c||^2 - 2 dot) -> fp64 rescue for near-ties ->
//          residual update + loss accum.
// x_q = x - final_residual. Loss = 2/(S*N*D) * sum(r_new^2) (codebook+commit, BETA=1).

#define D        128
#define C        256
#define ROWS     128
#define THREADS  512
#define MAXGRID  4096
#define EPS_GAP  1e-2f

__device__ float g_part[MAXGRID];

// dynamic smem layout (floats):
//   sR[ROWS*D] | cbT[D*C] | cnorm[C] | sIdx[ROWS] (int) | sIdxAll[ROWS*8] |
//   sRed[16] | sCnt[1] (int) | sList[ROWS] (int)
#define SMEM_FLOATS (ROWS*D + D*C + C + ROWS + ROWS*8 + 16 + 1 + ROWS)

__global__ void __launch_bounds__(THREADS, 1)
rvq_kernel(const float* __restrict__ x, const float* __restrict__ cbs,
           float* __restrict__ out, int N, int S)
{
    extern __shared__ float sm[];
    float* sR      = sm;                         // ROWS*D
    float* cbT     = sR + ROWS * D;              // D*C, element (k,c) at [k*C + (c ^ ((k&31)<<2))]
    float* cnorm   = cbT + D * C;                // C
    int*   sIdx    = (int*)(cnorm + C);          // ROWS
    float* sIdxAll = (float*)(sIdx + ROWS);      // ROWS*8
    float* sRed    = sIdxAll + ROWS * 8;         // 16
    int*   sCnt    = (int*)(sRed + 16);          // 1
    int*   sList   = sCnt + 1;                   // ROWS

    const int tid  = threadIdx.x;
    const int lane = tid & 31;
    const int w    = tid >> 5;                   // warp id 0..15
    const long long rowBase = (long long)blockIdx.x * ROWS;

    // ---- load x tile into sR (coalesced float4) ----
    const float4* xg  = (const float4*)(x + rowBase * D);
    float4*       sR4 = (float4*)sR;
    #pragma unroll
    for (int it = 0; it < (ROWS * D / 4) / THREADS; ++it)
        sR4[tid + it * THREADS] = xg[tid + it * THREADS];

    float lsum = 0.f;

    const int ty     = w;            // row group
    const int cbase0 = lane * 4;     // code quad base (codes 0..127); quad1 = +128

    for (int s = 0; s < S; ++s) {
        __syncthreads();                 // prev stage done with cbT / sR
        if (tid < C) cnorm[tid] = 0.f;
        if (tid == 0) *sCnt = 0;
        __syncthreads();

        // ---- load stage codebook -> cbT (swizzled) + cnorm ----
        {
            const float* cb   = cbs + (size_t)s * C * D;
            const int code    = ((w & 7) << 5) + lane;   // 0..255
            const int kqBase  = (w >> 3) * 16;           // 0 or 16
            float psum = 0.f;
            #pragma unroll
            for (int t = 0; t < 16; ++t) {
                const int kq = kqBase + t;
                const float4 v = *(const float4*)(cb + code * D + 4 * kq);
                const int k0 = 4 * kq;
                cbT[(k0 + 0) * C + (code ^ (((k0 + 0) & 31) << 2))] = v.x;
                cbT[(k0 + 1) * C + (code ^ (((k0 + 1) & 31) << 2))] = v.y;
                cbT[(k0 + 2) * C + (code ^ (((k0 + 2) & 31) << 2))] = v.z;
                cbT[(k0 + 3) * C + (code ^ (((k0 + 3) & 31) << 2))] = v.w;
                psum += v.x * v.x + v.y * v.y + v.z * v.z + v.w * v.w;
            }
            atomicAdd(&cnorm[code], psum);   // exactly 2 adders/code: commutative -> deterministic
        }
        __syncthreads();

        // ---- GEMM: acc[i][j] = dot(r[ty+16i], code j) ----
        float acc[8][8];
        #pragma unroll
        for (int i = 0; i < 8; ++i)
            #pragma unroll
            for (int j = 0; j < 8; ++j) acc[i][j] = 0.f;

        for (int k0 = 0; k0 < D; k0 += 4) {
            float4 rv[8];
            #pragma unroll
            for (int i = 0; i < 8; ++i)
                rv[i] = *(const float4*)&sR[(ty + 16 * i) * D + k0];
            #pragma unroll
            for (int m = 0; m < 4; ++m) {
                const int k  = k0 + m;
                const int sw = (k & 31) << 2;
                const float4 c0 = *(const float4*)&cbT[k * C + (cbase0 ^ sw)];
                const float4 c1 = *(const float4*)&cbT[k * C + 128 + (cbase0 ^ sw)];
                #pragma unroll
                for (int i = 0; i < 8; ++i) {
                    const float r = (m == 0) ? rv[i].x : (m == 1) ? rv[i].y
                                  : (m == 2) ? rv[i].z : rv[i].w;
                    acc[i][0] += r * c0.x;  acc[i][1] += r * c0.y;
                    acc[i][2] += r * c0.z;  acc[i][3] += r * c0.w;
                    acc[i][4] += r * c1.x;  acc[i][5] += r * c1.y;
                    acc[i][6] += r * c1.z;  acc[i][7] += r * c1.w;
                }
            }
        }

        // ---- argmin + second-best over 256 codes per row ----
        const float4 cn0 = *(const float4*)&cnorm[cbase0];
        const float4 cn1 = *(const float4*)&cnorm[128 + cbase0];
        #pragma unroll
        for (int i = 0; i < 8; ++i) {
            float sc[8];
            sc[0] = cn0.x - 2.f * acc[i][0];
            sc[1] = cn0.y - 2.f * acc[i][1];
            sc[2] = cn0.z - 2.f * acc[i][2];
            sc[3] = cn0.w - 2.f * acc[i][3];
            sc[4] = cn1.x - 2.f * acc[i][4];
            sc[5] = cn1.y - 2.f * acc[i][5];
            sc[6] = cn1.z - 2.f * acc[i][6];
            sc[7] = cn1.w - 2.f * acc[i][7];
            float b1 = sc[0], b2 = 3.4e38f;
            int   bi = cbase0;
            #pragma unroll
            for (int j = 1; j < 8; ++j) {
                const int idx = (j < 4) ? (cbase0 + j) : (128 + cbase0 + (j - 4));
                if (sc[j] < b1)      { b2 = b1; b1 = sc[j]; bi = idx; }
                else if (sc[j] < b2) { b2 = sc[j]; }
            }
            #pragma unroll
            for (int off = 16; off; off >>= 1) {
                const float ov1 = __shfl_down_sync(0xffffffffu, b1, off);
                const int   oi  = __shfl_down_sync(0xffffffffu, bi, off);
                const float ov2 = __shfl_down_sync(0xffffffffu, b2, off);
                const float m2  = fminf(fmaxf(b1, ov1), fminf(b2, ov2));
                if (ov1 < b1 || (ov1 == b1 && oi < bi)) { b1 = ov1; bi = oi; }
                b2 = m2;
            }
            if (lane == 0) {
                const int row = ty + 16 * i;
                sIdx[row] = bi;
                sIdxAll[row * 8 + s] = (float)bi;
                if (b2 - b1 < EPS_GAP) {
                    const int pos = atomicAdd(sCnt, 1);
                    sList[pos] = row;
                }
            }
        }
        __syncthreads();

        // ---- fp64 rescue for near-tie rows (rare) ----
        {
            const int cnt = *sCnt;
            for (int e = w; e < cnt; e += THREADS / 32) {
                const int row = sList[e];
                const float* rrow = &sR[row * D];
                double bestd = 1e300;
                int bestidx = 0;
                for (int j = lane; j < C; j += 32) {   // ascending j per lane
                    double dsum = 0.0;
                    for (int k = 0; k < D; ++k) {
                        const float cv = cbT[k * C + (j ^ ((k & 31) << 2))];
                        const double diff = (double)rrow[k] - (double)cv;
                        dsum = fma(diff, diff, dsum);
                    }
                    if (dsum < bestd) { bestd = dsum; bestidx = j; }
                }
                #pragma unroll
                for (int off = 16; off; off >>= 1) {
                    const double ov = __shfl_down_sync(0xffffffffu, bestd, off);
                    const int    oi = __shfl_down_sync(0xffffffffu, bestidx, off);
                    if (ov < bestd || (ov == bestd && oi < bestidx)) { bestd = ov; bestidx = oi; }
                }
                if (lane == 0) {
                    sIdx[row] = bestidx;
                    sIdxAll[row * 8 + s] = (float)bestidx;
                }
            }
        }
        __syncthreads();

        // ---- residual update + loss ----
        #pragma unroll
        for (int it = 0; it < (ROWS * D) / THREADS; ++it) {
            const int e   = tid + it * THREADS;
            const int row = e >> 7, k = e & 127;
            const int idx = sIdx[row];
            const float cv = cbT[k * C + (idx ^ ((k & 31) << 2))];
            const float r  = sR[e] - cv;
            sR[e] = r;
            lsum += r * r;
        }
    }
    __syncthreads();

    // ---- per-CTA loss partial (deterministic reduce happens in kernel 2) ----
    #pragma unroll
    for (int off = 16; off; off >>= 1)
        lsum += __shfl_down_sync(0xffffffffu, lsum, off);
    if (lane == 0) sRed[w] = lsum;
    __syncthreads();
    if (tid == 0) {
        float t = 0.f;
        #pragma unroll
        for (int i = 0; i < THREADS / 32; ++i) t += sRed[i];
        g_part[blockIdx.x] = t;
    }

    // ---- x_q = x - final residual ----
    float4* og = (float4*)(out + rowBase * D);
    #pragma unroll
    for (int it = 0; it < (ROWS * D / 4) / THREADS; ++it) {
        const float4 xv = xg[tid + it * THREADS];
        const float4 rv = sR4[tid + it * THREADS];
        float4 o;
        o.x = xv.x - rv.x; o.y = xv.y - rv.y; o.z = xv.z - rv.z; o.w = xv.w - rv.w;
        og[tid + it * THREADS] = o;
    }

    // ---- indices (float) ----
    float* oIdx = out + (size_t)N * D + 1;
    for (int e = tid; e < ROWS * S; e += THREADS) {
        const int row = e / S, st = e % S;
        oIdx[(rowBase + row) * S + st] = sIdxAll[row * 8 + st];
    }
}

__global__ void loss_reduce(float* __restrict__ out, long long off, int nPart, float scale)
{
    __shared__ float sr[32];
    float s = 0.f;
    for (int i = threadIdx.x; i < nPart; i += blockDim.x) s += g_part[i];
    #pragma unroll
    for (int o = 16; o; o >>= 1) s += __shfl_down_sync(0xffffffffu, s, o);
    if ((threadIdx.x & 31) == 0) sr[threadIdx.x >> 5] = s;
    __syncthreads();
    if (threadIdx.x == 0) {
        float t = 0.f;
        for (int i = 0; i < (int)blockDim.x / 32; ++i) t += sr[i];
        out[off] = t * scale;
    }
}

extern "C" void kernel_launch(void* const* d_in, const int* in_sizes, int n_in,
                              void* d_out, int out_size)
{
    const float* x   = (const float*)d_in[0];
    const float* cbs = (const float*)d_in[1];
    float* out = (float*)d_out;

    const int N = in_sizes[0] / D;              // 262144
    const int S = in_sizes[1] / (C * D);        // 4
    const int nBlocks = N / ROWS;               // 2048

    const size_t smemBytes = SMEM_FLOATS * sizeof(float);
    cudaFuncSetAttribute(rvq_kernel, cudaFuncAttributeMaxDynamicSharedMemorySize,
                         (int)smemBytes);

    rvq_kernel<<<nBlocks, THREADS, smemBytes>>>(x, cbs, out, N, S);

    const float scale = 2.f / ((float)S * (float)N * (float)D);
    loss_reduce<<<1, 256>>>(out, (long long)N * D, nBlocks, scale);
}

// round 3
// speedup vs baseline: 1.0636x; 1.0636x over previous
#include <cuda_runtime.h>

// Residual VQ: x [N,128] fp32, codebooks [S,256,128] fp32.
// Output layout (float32): x_q [N*128], mean_loss [1], indices [N*S] (as floats).
//
// One CTA processes 128 rows through all S stages:
//   stage: load codebook (swizzled, transposed) into SMEM -> GEMM dots (packed
//   fma.rn.f32x2, 2 codes per accumulator) -> argmin(||c||^2 - 2 dot) ->
//   fp64 rescue for near-ties -> residual update + loss accum.
// x_q = x - final_residual. Loss = 2/(S*N*D) * sum(r_new^2), reduced by the
// last CTA (ticket pattern, fixed-order sum -> deterministic).

#define D        128
#define C        256
#define ROWS     128
#define THREADS  512
#define MAXGRID  4096
#define EPS_GAP  1e-2f

__device__ float        g_part[MAXGRID];
__device__ unsigned int g_cnt = 0;

// dynamic smem layout (floats):
//   sR[ROWS*D] | cbT[D*C] | cnorm[C] | sIdx[ROWS] (int) | sIdxAll[ROWS*8] |
//   sRed[16] | sCnt[1] (int) | sList[ROWS] (int)
#define SMEM_FLOATS (ROWS*D + D*C + C + ROWS + ROWS*8 + 16 + 1 + ROWS)

#define FMA2(d, a, b) \
    asm("fma.rn.f32x2 %0, %1, %2, %3;" : "=l"(d) : "l"(a), "l"(b), "l"(d))

__global__ void __launch_bounds__(THREADS, 1)
rvq_kernel(const float* __restrict__ x, const float* __restrict__ cbs,
           float* __restrict__ out, int N, int S)
{
    extern __shared__ float sm[];
    float* sR      = sm;                         // ROWS*D
    float* cbT     = sR + ROWS * D;              // D*C, element (k,c) at [k*C + (c ^ ((k&31)<<2))]
    float* cnorm   = cbT + D * C;                // C
    int*   sIdx    = (int*)(cnorm + C);          // ROWS
    float* sIdxAll = (float*)(sIdx + ROWS);      // ROWS*8
    float* sRed    = sIdxAll + ROWS * 8;         // 16
    int*   sCnt    = (int*)(sRed + 16);          // 1
    int*   sList   = sCnt + 1;                   // ROWS
    __shared__ int sLast;

    const int tid  = threadIdx.x;
    const int lane = tid & 31;
    const int w    = tid >> 5;                   // warp id 0..15
    const long long rowBase = (long long)blockIdx.x * ROWS;

    // ---- load x tile into sR (coalesced float4) ----
    const float4* xg  = (const float4*)(x + rowBase * D);
    float4*       sR4 = (float4*)sR;
    #pragma unroll
    for (int it = 0; it < (ROWS * D / 4) / THREADS; ++it)
        sR4[tid + it * THREADS] = xg[tid + it * THREADS];

    float lsum = 0.f;

    const int ty     = w;            // row group
    const int cbase0 = lane * 4;     // code quad base (codes 0..127); quad1 = +128

    for (int s = 0; s < S; ++s) {
        __syncthreads();                 // prev stage done with cbT / sR
        if (tid < C) cnorm[tid] = 0.f;
        if (tid == 0) *sCnt = 0;
        __syncthreads();

        // ---- load stage codebook -> cbT (swizzled) + cnorm ----
        {
            const float* cb   = cbs + (size_t)s * C * D;
            const int code    = ((w & 7) << 5) + lane;   // 0..255
            const int kqBase  = (w >> 3) * 16;           // 0 or 16
            float psum = 0.f;
            #pragma unroll
            for (int t = 0; t < 16; ++t) {
                const int kq = kqBase + t;
                const float4 v = *(const float4*)(cb + code * D + 4 * kq);
                const int k0 = 4 * kq;
                cbT[(k0 + 0) * C + (code ^ (((k0 + 0) & 31) << 2))] = v.x;
                cbT[(k0 + 1) * C + (code ^ (((k0 + 1) & 31) << 2))] = v.y;
                cbT[(k0 + 2) * C + (code ^ (((k0 + 2) & 31) << 2))] = v.z;
                cbT[(k0 + 3) * C + (code ^ (((k0 + 3) & 31) << 2))] = v.w;
                psum += v.x * v.x + v.y * v.y + v.z * v.z + v.w * v.w;
            }
            atomicAdd(&cnorm[code], psum);   // exactly 2 adders/code: commutative -> deterministic
        }
        __syncthreads();

        // ---- GEMM: packed f32x2, acc2[i][p] = dots for code pair p of row ty+16i ----
        // pair map: [0]=(cbase0,+1) [1]=(cbase0+2,+3) [2]=(128+cbase0,+1) [3]=(128+cbase0+2,+3)
        unsigned long long acc2[8][4];
        #pragma unroll
        for (int i = 0; i < 8; ++i)
            #pragma unroll
            for (int p = 0; p < 4; ++p) acc2[i][p] = 0ULL;

        for (int k0 = 0; k0 < D; k0 += 4) {
            float4 rv[8];
            #pragma unroll
            for (int i = 0; i < 8; ++i)
                rv[i] = *(const float4*)&sR[(ty + 16 * i) * D + k0];
            #pragma unroll
            for (int m = 0; m < 4; ++m) {
                const int k  = k0 + m;
                const int sw = (k & 31) << 2;
                const ulonglong2 c0 = *(const ulonglong2*)&cbT[k * C + (cbase0 ^ sw)];
                const ulonglong2 c1 = *(const ulonglong2*)&cbT[k * C + 128 + (cbase0 ^ sw)];
                #pragma unroll
                for (int i = 0; i < 8; ++i) {
                    const float r = (m == 0) ? rv[i].x : (m == 1) ? rv[i].y
                                  : (m == 2) ? rv[i].z : rv[i].w;
                    unsigned long long rr;
                    asm("mov.b64 %0, {%1, %1};" : "=l"(rr) : "f"(r));
                    FMA2(acc2[i][0], rr, c0.x);
                    FMA2(acc2[i][1], rr, c0.y);
                    FMA2(acc2[i][2], rr, c1.x);
                    FMA2(acc2[i][3], rr, c1.y);
                }
            }
        }

        // ---- argmin + second-best over 256 codes per row ----
        const float4 cn0 = *(const float4*)&cnorm[cbase0];
        const float4 cn1 = *(const float4*)&cnorm[128 + cbase0];
        #pragma unroll
        for (int i = 0; i < 8; ++i) {
            float d0, d1, sc[8];
            asm("mov.b64 {%0, %1}, %2;" : "=f"(d0), "=f"(d1) : "l"(acc2[i][0]));
            sc[0] = cn0.x - 2.f * d0;  sc[1] = cn0.y - 2.f * d1;
            asm("mov.b64 {%0, %1}, %2;" : "=f"(d0), "=f"(d1) : "l"(acc2[i][1]));
            sc[2] = cn0.z - 2.f * d0;  sc[3] = cn0.w - 2.f * d1;
            asm("mov.b64 {%0, %1}, %2;" : "=f"(d0), "=f"(d1) : "l"(acc2[i][2]));
            sc[4] = cn1.x - 2.f * d0;  sc[5] = cn1.y - 2.f * d1;
            asm("mov.b64 {%0, %1}, %2;" : "=f"(d0), "=f"(d1) : "l"(acc2[i][3]));
            sc[6] = cn1.z - 2.f * d0;  sc[7] = cn1.w - 2.f * d1;

            float b1 = sc[0], b2 = 3.4e38f;
            int   bi = cbase0;
            #pragma unroll
            for (int j = 1; j < 8; ++j) {
                const int idx = (j < 4) ? (cbase0 + j) : (128 + cbase0 + (j - 4));
                if (sc[j] < b1)      { b2 = b1; b1 = sc[j]; bi = idx; }
                else if (sc[j] < b2) { b2 = sc[j]; }
            }
            #pragma unroll
            for (int off = 16; off; off >>= 1) {
                const float ov1 = __shfl_down_sync(0xffffffffu, b1, off);
                const int   oi  = __shfl_down_sync(0xffffffffu, bi, off);
                const float ov2 = __shfl_down_sync(0xffffffffu, b2, off);
                const float m2  = fminf(fmaxf(b1, ov1), fminf(b2, ov2));
                if (ov1 < b1 || (ov1 == b1 && oi < bi)) { b1 = ov1; bi = oi; }
                b2 = m2;
            }
            if (lane == 0) {
                const int row = ty + 16 * i;
                sIdx[row] = bi;
                sIdxAll[row * 8 + s] = (float)bi;
                if (b2 - b1 < EPS_GAP) {
                    const int pos = atomicAdd(sCnt, 1);
                    sList[pos] = row;
                }
            }
        }
        __syncthreads();

        // ---- fp64 rescue for near-tie rows (rare) ----
        {
            const int cnt = *sCnt;
            for (int e = w; e < cnt; e += THREADS / 32) {
                const int row = sList[e];
                const float* rrow = &sR[row * D];
                double bestd = 1e300;
                int bestidx = 0;
                for (int j = lane; j < C; j += 32) {   // ascending j per lane
                    double dsum = 0.0;
                    for (int k = 0; k < D; ++k) {
                        const float cv = cbT[k * C + (j ^ ((k & 31) << 2))];
                        const double diff = (double)rrow[k] - (double)cv;
                        dsum = fma(diff, diff, dsum);
                    }
                    if (dsum < bestd) { bestd = dsum; bestidx = j; }
                }
                #pragma unroll
                for (int off = 16; off; off >>= 1) {
                    const double ov = __shfl_down_sync(0xffffffffu, bestd, off);
                    const int    oi = __shfl_down_sync(0xffffffffu, bestidx, off);
                    if (ov < bestd || (ov == bestd && oi < bestidx)) { bestd = ov; bestidx = oi; }
                }
                if (lane == 0) {
                    sIdx[row] = bestidx;
                    sIdxAll[row * 8 + s] = (float)bestidx;
                }
            }
        }
        __syncthreads();

        // ---- residual update + loss ----
        #pragma unroll
        for (int it = 0; it < (ROWS * D) / THREADS; ++it) {
            const int e   = tid + it * THREADS;
            const int row = e >> 7, k = e & 127;
            const int idx = sIdx[row];
            const float cv = cbT[k * C + (idx ^ ((k & 31) << 2))];
            const float r  = sR[e] - cv;
            sR[e] = r;
            lsum += r * r;
        }
    }
    __syncthreads();

    // ---- x_q = x - final residual ----
    float4* og = (float4*)(out + rowBase * D);
    #pragma unroll
    for (int it = 0; it < (ROWS * D / 4) / THREADS; ++it) {
        const float4 xv = xg[tid + it * THREADS];
        const float4 rv = sR4[tid + it * THREADS];
        float4 o;
        o.x = xv.x - rv.x; o.y = xv.y - rv.y; o.z = xv.z - rv.z; o.w = xv.w - rv.w;
        og[tid + it * THREADS] = o;
    }

    // ---- indices (float) ----
    float* oIdx = out + (size_t)N * D + 1;
    for (int e = tid; e < ROWS * S; e += THREADS) {
        const int row = e / S, st = e % S;
        oIdx[(rowBase + row) * S + st] = sIdxAll[row * 8 + st];
    }

    // ---- per-CTA loss partial ----
    #pragma unroll
    for (int off = 16; off; off >>= 1)
        lsum += __shfl_down_sync(0xffffffffu, lsum, off);
    if (lane == 0) sRed[w] = lsum;
    __syncthreads();
    if (tid == 0) {
        float t = 0.f;
        #pragma unroll
        for (int i = 0; i < THREADS / 32; ++i) t += sRed[i];
        g_part[blockIdx.x] = t;
        __threadfence();
        const unsigned int ticket = atomicAdd(&g_cnt, 1u);
        sLast = (ticket == (unsigned int)gridDim.x - 1u) ? 1 : 0;
    }
    __syncthreads();

    // ---- last CTA: deterministic fixed-order loss reduction ----
    if (sLast) {
        __threadfence();
        const int nPart = gridDim.x;
        float ssum = 0.f;
        for (int i = tid; i < nPart; i += THREADS) ssum += g_part[i];
        #pragma unroll
        for (int off = 16; off; off >>= 1)
            ssum += __shfl_down_sync(0xffffffffu, ssum, off);
        if (lane == 0) sRed[w] = ssum;
        __syncthreads();
        if (tid == 0) {
            float t = 0.f;
            #pragma unroll
            for (int i = 0; i < THREADS / 32; ++i) t += sRed[i];
            const float scale = 2.f / ((float)S * (float)N * (float)D);
            out[(size_t)N * D] = t * scale;
            g_cnt = 0;                       // reset for next graph replay
        }
    }
}

extern "C" void kernel_launch(void* const* d_in, const int* in_sizes, int n_in,
                              void* d_out, int out_size)
{
    const float* x   = (const float*)d_in[0];
    const float* cbs = (const float*)d_in[1];
    float* out = (float*)d_out;

    const int N = in_sizes[0] / D;              // 262144
    const int S = in_sizes[1] / (C * D);        // 4
    const int nBlocks = N / ROWS;               // 2048

    const size_t smemBytes = SMEM_FLOATS * sizeof(float);
    cudaFuncSetAttribute(rvq_kernel, cudaFuncAttributeMaxDynamicSharedMemorySize,
                         (int)smemBytes);

    rvq_kernel<<<nBlocks, THREADS, smemBytes>>>(x, cbs, out, N, S);
}